// round 10
// baseline (speedup 1.0000x reference)
#include <cuda_runtime.h>
#include <cuda_fp16.h>

// DilationLayerExtSE: out[b,c,h,w] = max_{di,dj in 5x5}( zeropad2(x)[h+di,w+dj] + w[b,c,di,dj] ) + bias[b,c]
// x [8,128,128,128] f32. stride=1, pad=2.
//
// R10: fp16 HADD2/HMAX2 tree fold + smem fp16 tile, scheduling fixes:
//   - QUARTER-plane blocks: 4096 blocks x 128 thr, 32 output rows each
//     (36-row x 136-half tile, 9.8KB) -> 3.46 waves (86% avg fill vs 73%).
//   - halo-only zero-fill (disjoint from valid fill) -> ONE __syncthreads.
//   - acc[4][4] direct-indexed in-flight window (oh always 0..3).
//   Thread = 8 output cols x 4 output rows; bias folded into fp16 weights.
//   Zero padding: OOB gives x=0 (reference zero-pads BEFORE +w).
//   Layout: global col c <-> tile half index c+4 (left halo at halves 2,3).

#define H_DIM 128
#define W_DIM 128
#define TROWS 36            // 32 output rows + 2 halo each side
#define TPITCH 136          // halves per tile row; /2 = 68 half2
#define TP2 (TPITCH / 2)

__device__ __forceinline__ unsigned h2u(__half2 v) {
    return *reinterpret_cast<unsigned*>(&v);
}
__device__ __forceinline__ __half2 u2h(unsigned v) {
    return *reinterpret_cast<__half2*>(&v);
}
// (a.y, b.x) — one PRMT
__device__ __forceinline__ __half2 h2shift(__half2 a, __half2 b) {
    return u2h(__byte_perm(h2u(a), h2u(b), 0x5432));
}

__global__ __launch_bounds__(128, 8)
void dilation_kernel(const float* __restrict__ x,
                     const float* __restrict__ wgt,
                     const float* __restrict__ bias,
                     float* __restrict__ out) {
    __shared__ __half2 s_tile[TROWS * TP2];          // 9792 B

    const int blk   = blockIdx.x;            // 0..4095
    const int plane = blk >> 2;              // b*C + c
    const int q     = blk & 3;               // quarter (32 rows)
    const int tid   = threadIdx.x;
    const int cg    = tid & 15;              // column group 0..15 (8 cols)
    const int strip = tid >> 4;              // 0..7 (4 rows each)
    const int colbase = cg << 3;

    const float* __restrict__ xpl = x   + (size_t)plane * (H_DIM * W_DIM);
    float*       __restrict__ op  = out + (size_t)plane * (H_DIM * W_DIM) + colbase;
    const float* __restrict__ wp  = wgt + plane * 25;
    const float b = __ldg(&bias[plane]);

    // fp16 weights with bias folded (single rounding of w+b)
    __half2 wh[25];
#pragma unroll
    for (int k = 0; k < 25; ++k) wh[k] = __float2half2_rn(__ldg(&wp[k]) + b);

    const __half2 z2 = __floats2half2_rn(0.f, 0.f);
    const int rtile0 = q * 32 - 2;            // global row of tile row 0

    // ---- halo-only zero fill (disjoint from valid-region fill) ----
    // side halos: half2 idx 1 (halves 2,3) and 66 (halves 132,133), all rows
    for (int i = tid; i < TROWS * 2; i += 128) {
        const int row  = i >> 1;
        const int side = i & 1;
        s_tile[row * TP2 + (side ? 66 : 1)] = z2;
    }
    // image-edge rows (entire used width, half2 idx 1..66)
    if (q == 0) {
        for (int i = tid; i < 2 * 66; i += 128)
            s_tile[(i / 66) * TP2 + 1 + (i % 66)] = z2;
    } else if (q == 3) {
        for (int i = tid; i < 2 * 66; i += 128)
            s_tile[(34 + i / 66) * TP2 + 1 + (i % 66)] = z2;
    }

    // ---- valid-region fill: global col c -> half index c+4 ----
    for (int i = tid; i < TROWS * 32; i += 128) {
        const int row = i >> 5;
        const int g   = i & 31;               // float4 group: cols 4g..4g+3
        const int r   = rtile0 + row;
        if ((unsigned)r < (unsigned)H_DIM) {
            const float4 v = __ldg(reinterpret_cast<const float4*>(xpl + r * W_DIM + g * 4));
            const int bi = row * TP2 + 2 + g * 2;
            s_tile[bi]     = __floats2half2_rn(v.x, v.y);
            s_tile[bi + 1] = __floats2half2_rn(v.z, v.w);
        }
    }
    __syncthreads();

    // ---- fold loop: no predicates, no global loads ----
    // pair j (cols colbase-2+j, colbase-1+j) at half idx strip*4*TPITCH + t*TPITCH + 2 + colbase + j
    const __half* s_base = reinterpret_cast<const __half*>(s_tile)
                         + strip * 4 * TPITCH + 2 + colbase;

    __half2 acc[4][4];                        // 4 in-flight output rows x 4 pairs

#pragma unroll
    for (int t = 0; t < 8; ++t) {
        const __half* rp = s_base + t * TPITCH;

        __half2 pairs[11];
#pragma unroll
        for (int i = 0; i < 6; ++i)
            pairs[2 * i] = *reinterpret_cast<const __half2*>(rp + 2 * i);
#pragma unroll
        for (int i = 0; i < 5; ++i)
            pairs[2 * i + 1] = h2shift(pairs[2 * i], pairs[2 * i + 2]);

        // fold into in-flight outputs oh = t-di (weight row di), tree max
#pragma unroll
        for (int di = 0; di < 5; ++di) {
            const int oh = t - di;
            if (oh < 0 || oh > 3) continue;   // compile-time pruned
            __half2* a = acc[oh];
            const __half2* w = &wh[di * 5];
#pragma unroll
            for (int p = 0; p < 4; ++p) {
                const __half2 m01 = __hmax2(__hadd2(pairs[2 * p],     w[0]),
                                            __hadd2(pairs[2 * p + 1], w[1]));
                const __half2 m23 = __hmax2(__hadd2(pairs[2 * p + 2], w[2]),
                                            __hadd2(pairs[2 * p + 3], w[3]));
                const __half2 m4  = __hadd2(pairs[2 * p + 4], w[4]);
                const __half2 m   = __hmax2(__hmax2(m01, m23), m4);
                a[p] = (di == 0) ? m : __hmax2(a[p], m);
            }
        }

        // output row oh = t-4 complete: convert to fp32, store
        if (t >= 4) {
            const int oh = t - 4;
            const __half2* a = acc[oh];
            float* orow = op + (size_t)(q * 32 + strip * 4 + oh) * W_DIM;
            const float2 f0 = __half22float2(a[0]);
            const float2 f1 = __half22float2(a[1]);
            const float2 f2 = __half22float2(a[2]);
            const float2 f3 = __half22float2(a[3]);
            *reinterpret_cast<float4*>(orow)     = make_float4(f0.x, f0.y, f1.x, f1.y);
            *reinterpret_cast<float4*>(orow + 4) = make_float4(f2.x, f2.y, f3.x, f3.y);
        }
    }
}

extern "C" void kernel_launch(void* const* d_in, const int* in_sizes, int n_in,
                              void* d_out, int out_size) {
    (void)in_sizes; (void)n_in; (void)out_size;
    const float* x    = (const float*)d_in[0];   // [8,128,128,128]
    const float* wgt  = (const float*)d_in[1];   // [8,128,5,5]
    const float* bias = (const float*)d_in[2];   // [8,128]
    float* out = (float*)d_out;                  // [8,128,128,128]

    dilation_kernel<<<4096, 128>>>(x, wgt, bias, out);
}

// round 11
// speedup vs baseline: 1.0105x; 1.0105x over previous
#include <cuda_runtime.h>
#include <cuda_fp16.h>

// DilationLayerExtSE: out[b,c,h,w] = max_{di,dj in 5x5}( zeropad2(x)[h+di,w+dj] + w[b,c,di,dj] ) + bias[b,c]
// x [8,128,128,128] f32. stride=1, pad=2.
//
// R11 = R9 (best: half-plane smem fp16 tile, HADD2/HMAX2 tree fold)
//   + halo-only zero-fill with ONE __syncthreads (prologue trim)
//   + tile layout shifted so even pairs are 8B-aligned: 3 LDS.64 per row
//     instead of 6 LDS.32.
// Block = half plane: 2048 blocks x 128 thr; thread = 8 cols x 8 rows,
// 12 fold iterations, 5 in-flight acc rows. Bias folded into fp16 weights.
// Layout: global col c <-> half index c+6 (left halo at halves 4,5;
// right halo at 134,135; halves 0-3 unused). Tile 68 x 136 halves = 18.5KB.
// Zero padding: OOB gives x=0 (reference zero-pads BEFORE +w).

#define H_DIM 128
#define W_DIM 128
#define TROWS 68            // 64 output rows + 2 halo each side
#define TPITCH 136          // halves per tile row
#define TP2 (TPITCH / 2)    // 68 half2 per row

__device__ __forceinline__ unsigned h2u(__half2 v) {
    return *reinterpret_cast<unsigned*>(&v);
}
__device__ __forceinline__ __half2 u2h(unsigned v) {
    return *reinterpret_cast<__half2*>(&v);
}
// (a.y, b.x) — one PRMT
__device__ __forceinline__ __half2 h2shift(__half2 a, __half2 b) {
    return u2h(__byte_perm(h2u(a), h2u(b), 0x5432));
}

__global__ __launch_bounds__(128, 8)
void dilation_kernel(const float* __restrict__ x,
                     const float* __restrict__ wgt,
                     const float* __restrict__ bias,
                     float* __restrict__ out) {
    __shared__ __half2 s_tile[TROWS * TP2];          // 18496 B

    const int blk   = blockIdx.x;            // 0..2047
    const int plane = blk >> 1;              // b*C + c
    const int half  = blk & 1;
    const int tid   = threadIdx.x;
    const int cg    = tid & 15;              // column group 0..15 (8 cols)
    const int strip = tid >> 4;              // 0..7 (8 rows each)
    const int colbase = cg << 3;

    const float* __restrict__ xpl = x   + (size_t)plane * (H_DIM * W_DIM);
    float*       __restrict__ op  = out + (size_t)plane * (H_DIM * W_DIM) + colbase;
    const float* __restrict__ wp  = wgt + plane * 25;
    const float b = __ldg(&bias[plane]);

    // fp16 weights with bias folded (single rounding of w+b)
    __half2 wh[25];
#pragma unroll
    for (int k = 0; k < 25; ++k) wh[k] = __float2half2_rn(__ldg(&wp[k]) + b);

    const __half2 z2 = __floats2half2_rn(0.f, 0.f);
    const int rtile0 = half * 64 - 2;         // global row of tile row 0

    // ---- halo-only zero fill (disjoint from valid-region fill) ----
    // side halos: half2 idx 2 (halves 4,5) and 67 (halves 134,135), all rows
    for (int i = tid; i < TROWS * 2; i += 128) {
        const int row  = i >> 1;
        const int side = i & 1;
        s_tile[row * TP2 + (side ? 67 : 2)] = z2;
    }
    // image-edge rows (used width: half2 idx 2..67 = 66 half2)
    if (half == 0) {
        for (int i = tid; i < 2 * 66; i += 128)
            s_tile[(i / 66) * TP2 + 2 + (i % 66)] = z2;
    } else {
        for (int i = tid; i < 2 * 66; i += 128)
            s_tile[(66 + i / 66) * TP2 + 2 + (i % 66)] = z2;
    }

    // ---- valid-region fill: global col c -> half index c+6 ----
    // float4 group g (cols 4g..4g+3) -> half2 idx 3 + 2g
    for (int i = tid; i < TROWS * 32; i += 128) {
        const int row = i >> 5;
        const int g   = i & 31;
        const int r   = rtile0 + row;
        if ((unsigned)r < (unsigned)H_DIM) {
            const float4 v = __ldg(reinterpret_cast<const float4*>(xpl + r * W_DIM + g * 4));
            const int bi = row * TP2 + 3 + g * 2;
            s_tile[bi]     = __floats2half2_rn(v.x, v.y);
            s_tile[bi + 1] = __floats2half2_rn(v.z, v.w);
        }
    }
    __syncthreads();

    // ---- fold loop: no predicates, no global loads ----
    // pair j (cols colbase-2+j ..) at half idx: row*TPITCH + colbase+4 + j
    // base byte = 16*cg + 8 -> even pairs 8B-aligned -> LDS.64
    const __half* s_base = reinterpret_cast<const __half*>(s_tile)
                         + strip * 8 * TPITCH + colbase + 4;

    __half2 acc[5][4];                        // 5 in-flight output rows x 4 pairs

#pragma unroll
    for (int t = 0; t < 12; ++t) {
        const __half* rp = s_base + t * TPITCH;

        __half2 pairs[11];
        {
            const uint2 u0 = *reinterpret_cast<const uint2*>(rp);      // pairs 0,2
            const uint2 u1 = *reinterpret_cast<const uint2*>(rp + 4);  // pairs 4,6
            const uint2 u2 = *reinterpret_cast<const uint2*>(rp + 8);  // pairs 8,10
            pairs[0]  = u2h(u0.x); pairs[2]  = u2h(u0.y);
            pairs[4]  = u2h(u1.x); pairs[6]  = u2h(u1.y);
            pairs[8]  = u2h(u2.x); pairs[10] = u2h(u2.y);
        }
#pragma unroll
        for (int i = 0; i < 5; ++i)
            pairs[2 * i + 1] = h2shift(pairs[2 * i], pairs[2 * i + 2]);

        // fold into in-flight outputs oh = t-di (weight row di), tree max
#pragma unroll
        for (int di = 0; di < 5; ++di) {
            const int oh = t - di;
            if (oh < 0 || oh > 7) continue;   // compile-time pruned
            __half2* a = acc[oh % 5];
            const __half2* w = &wh[di * 5];
#pragma unroll
            for (int p = 0; p < 4; ++p) {
                const __half2 m01 = __hmax2(__hadd2(pairs[2 * p],     w[0]),
                                            __hadd2(pairs[2 * p + 1], w[1]));
                const __half2 m23 = __hmax2(__hadd2(pairs[2 * p + 2], w[2]),
                                            __hadd2(pairs[2 * p + 3], w[3]));
                const __half2 m4  = __hadd2(pairs[2 * p + 4], w[4]);
                const __half2 m   = __hmax2(__hmax2(m01, m23), m4);
                a[p] = (di == 0) ? m : __hmax2(a[p], m);
            }
        }

        // output row oh = t-4 complete: convert to fp32, store
        if (t >= 4) {
            const int oh = t - 4;
            const __half2* a = acc[oh % 5];
            float* orow = op + (size_t)(half * 64 + strip * 8 + oh) * W_DIM;
            const float2 f0 = __half22float2(a[0]);
            const float2 f1 = __half22float2(a[1]);
            const float2 f2 = __half22float2(a[2]);
            const float2 f3 = __half22float2(a[3]);
            *reinterpret_cast<float4*>(orow)     = make_float4(f0.x, f0.y, f1.x, f1.y);
            *reinterpret_cast<float4*>(orow + 4) = make_float4(f2.x, f2.y, f3.x, f3.y);
        }
    }
}

extern "C" void kernel_launch(void* const* d_in, const int* in_sizes, int n_in,
                              void* d_out, int out_size) {
    (void)in_sizes; (void)n_in; (void)out_size;
    const float* x    = (const float*)d_in[0];   // [8,128,128,128]
    const float* wgt  = (const float*)d_in[1];   // [8,128,5,5]
    const float* bias = (const float*)d_in[2];   // [8,128]
    float* out = (float*)d_out;                  // [8,128,128,128]

    dilation_kernel<<<2048, 128>>>(x, wgt, bias, out);
}

// round 12
// speedup vs baseline: 1.2846x; 1.2713x over previous
#include <cuda_runtime.h>
#include <cuda_fp16.h>

// DilationLayerExtSE: out[b,c,h,w] = max_{di,dj in 5x5}( zeropad2(x)[h+di,w+dj] + w[b,c,di,dj] ) + bias[b,c]
// x [8,128,128,128] f32. stride=1, pad=2.
//
// R12 = R9 (best measured: half-plane smem fp16 tile, HADD2/HMAX2 tree fold,
//           full zero-fill + 2 barriers, LDS.32 pair loads) with EXACTLY ONE
//           change: the full-tile zero pass uses STS.128 (int4) instead of
//           STS.32 (36 -> 9 stores/thread). Control re-baseline after two
//           anomalous uniformly-slow rounds.
//   Block = half plane: 2048 x 128 thr; thread = 8 cols x 8 rows, 12 fold
//   iterations, 5 in-flight acc rows. Bias folded into fp16 weights.
//   Layout: global col c <-> tile half index c+4 (left halo halves 2,3).
//   Zero padding: OOB gives x=0 (reference zero-pads BEFORE +w).

#define H_DIM 128
#define W_DIM 128
#define TROWS 68            // 64 output rows + 2 halo each side
#define TPITCH 136          // halves per tile row (4 halo + 128 + pad), 272B
#define TP2 (TPITCH / 2)    // 68 half2 per row

__device__ __forceinline__ unsigned h2u(__half2 v) {
    return *reinterpret_cast<unsigned*>(&v);
}
__device__ __forceinline__ __half2 u2h(unsigned v) {
    return *reinterpret_cast<__half2*>(&v);
}
// (a.y, b.x) — one PRMT
__device__ __forceinline__ __half2 h2shift(__half2 a, __half2 b) {
    return u2h(__byte_perm(h2u(a), h2u(b), 0x5432));
}

__global__ __launch_bounds__(128, 8)
void dilation_kernel(const float* __restrict__ x,
                     const float* __restrict__ wgt,
                     const float* __restrict__ bias,
                     float* __restrict__ out) {
    __shared__ __half2 s_tile[TROWS * TP2];          // 18496 B

    const int blk   = blockIdx.x;            // 0..2047
    const int plane = blk >> 1;              // b*C + c
    const int half  = blk & 1;
    const int tid   = threadIdx.x;
    const int cg    = tid & 15;              // column group 0..15 (8 cols)
    const int strip = tid >> 4;              // 0..7 (8 rows each)
    const int colbase = cg << 3;

    const float* __restrict__ xpl = x   + (size_t)plane * (H_DIM * W_DIM);
    float*       __restrict__ op  = out + (size_t)plane * (H_DIM * W_DIM) + colbase;
    const float* __restrict__ wp  = wgt + plane * 25;
    const float b = __ldg(&bias[plane]);

    // fp16 weights with bias folded (single rounding of w+b)
    __half2 wh[25];
#pragma unroll
    for (int k = 0; k < 25; ++k) wh[k] = __float2half2_rn(__ldg(&wp[k]) + b);

    // ---- stage tile: vectorized zero-fill, then overwrite valid region ----
    {
        int4* zp = reinterpret_cast<int4*>(s_tile);
        const int4 z4 = make_int4(0, 0, 0, 0);
        // 18496 B / 16 = 1156 int4
        for (int i = tid; i < (TROWS * TPITCH * 2) / 16; i += 128) zp[i] = z4;
    }
    __syncthreads();

    const int rtile0 = half * 64 - 2;        // global row of tile row 0
#pragma unroll
    for (int i = tid; i < TROWS * 32; i += 128) {
        const int row = i >> 5;
        const int g   = i & 31;              // float4 group, cols 4g..4g+3
        const int r   = rtile0 + row;
        if ((unsigned)r < (unsigned)H_DIM) {
            const float4 v = __ldg(reinterpret_cast<const float4*>(xpl + r * W_DIM + g * 4));
            const int bi = row * TP2 + 2 + g * 2;  // half2 index
            s_tile[bi]     = __floats2half2_rn(v.x, v.y);
            s_tile[bi + 1] = __floats2half2_rn(v.z, v.w);
        }
    }
    __syncthreads();

    // ---- fold loop: no predicates, no global loads ----
    // pair j (cols colbase-2+j, colbase-1+j) at half idx:
    //   (strip*8+t)*TPITCH + 2 + colbase + j
    const __half* s_base = reinterpret_cast<const __half*>(s_tile)
                         + strip * 8 * TPITCH + 2 + colbase;

    __half2 acc[5][4];                       // 5 in-flight output rows x 4 pairs

#pragma unroll
    for (int t = 0; t < 12; ++t) {
        const __half* rp = s_base + t * TPITCH;

        __half2 pairs[11];
#pragma unroll
        for (int i = 0; i < 6; ++i)
            pairs[2 * i] = *reinterpret_cast<const __half2*>(rp + 2 * i);
#pragma unroll
        for (int i = 0; i < 5; ++i)
            pairs[2 * i + 1] = h2shift(pairs[2 * i], pairs[2 * i + 2]);

        // fold into in-flight outputs oh = t-di (weight row di), tree max
#pragma unroll
        for (int di = 0; di < 5; ++di) {
            const int oh = t - di;
            if (oh < 0 || oh > 7) continue;  // compile-time pruned
            __half2* a = acc[oh % 5];
            const __half2* w = &wh[di * 5];
#pragma unroll
            for (int p = 0; p < 4; ++p) {
                const __half2 m01 = __hmax2(__hadd2(pairs[2 * p],     w[0]),
                                            __hadd2(pairs[2 * p + 1], w[1]));
                const __half2 m23 = __hmax2(__hadd2(pairs[2 * p + 2], w[2]),
                                            __hadd2(pairs[2 * p + 3], w[3]));
                const __half2 m4  = __hadd2(pairs[2 * p + 4], w[4]);
                const __half2 m   = __hmax2(__hmax2(m01, m23), m4);
                a[p] = (di == 0) ? m : __hmax2(a[p], m);
            }
        }

        // output row oh = t-4 complete: convert to fp32, store (bias already in)
        if (t >= 4) {
            const int oh = t - 4;
            const __half2* a = acc[oh % 5];
            float* orow = op + (size_t)(half * 64 + strip * 8 + oh) * W_DIM;
            const float2 f0 = __half22float2(a[0]);
            const float2 f1 = __half22float2(a[1]);
            const float2 f2 = __half22float2(a[2]);
            const float2 f3 = __half22float2(a[3]);
            *reinterpret_cast<float4*>(orow)     = make_float4(f0.x, f0.y, f1.x, f1.y);
            *reinterpret_cast<float4*>(orow + 4) = make_float4(f2.x, f2.y, f3.x, f3.y);
        }
    }
}

extern "C" void kernel_launch(void* const* d_in, const int* in_sizes, int n_in,
                              void* d_out, int out_size) {
    (void)in_sizes; (void)n_in; (void)out_size;
    const float* x    = (const float*)d_in[0];   // [8,128,128,128]
    const float* wgt  = (const float*)d_in[1];   // [8,128,5,5]
    const float* bias = (const float*)d_in[2];   // [8,128]
    float* out = (float*)d_out;                  // [8,128,128,128]

    dilation_kernel<<<2048, 128>>>(x, wgt, bias, out);
}